// round 7
// baseline (speedup 1.0000x reference)
#include <cuda_runtime.h>
#include <cuda_bf16.h>

#define N_NODES 50000
#define D 128
#define N_EDGES 640000
#define S_BLK 64                       // sort blocks (wave-1 resident: < 148)
#define GRID_TOT 296                   // 2 CTA/SM * 148 SM, all co-resident
#define NGB ((N_NODES + 127) / 128)    // 391 gemm tiles
#define CHUNK 4                        // scan items per sort thread

// Packed fp32x2 FMA (sm_100+): d = a*b + d, two lane-FMAs per fma-pipe slot.
#define FMA2(acc, a, b) \
    asm("fma.rn.f32x2 %0, %1, %2, %0;" : "+l"(acc) : "l"(a), "l"(b))
#define SPLAT2(d, f) \
    asm("mov.b64 %0, {%1, %1};" : "=l"(d) : "f"(f))
#define UNPACK2(lo, hi, v) \
    asm("mov.b64 {%0, %1}, %2;" : "=f"(lo), "=f"(hi) : "l"(v))

// ---- device scratch (no allocs allowed; zero-initialized) ----
__device__ float g_Y[(size_t)N_NODES * D];   // feat @ W   (25.6 MB)
__device__ int   g_count[N_NODES];           // degree histogram
__device__ int   g_offset[N_NODES];          // global excl. prefix; scatter mutates to end
__device__ int   g_bsum[S_BLK];              // per-sort-block totals
__device__ int   g_bbase[S_BLK];             // excl. scan of block totals
__device__ int   g_src_sorted[N_EDGES];      // src index grouped by dst
__device__ int   g_is64;                     // 1 if edge indices are int64
__device__ unsigned g_bar_cnt;               // sort barrier arrivals
__device__ unsigned g_tile;                  // gemm tile work-stealing counter
__device__ unsigned g_done;                  // end-of-kernel reset ticket

// Global spin barrier among the S_BLK sort blocks. target = phase * S_BLK.
__device__ __forceinline__ void sort_barrier(unsigned target) {
    __syncthreads();
    if (threadIdx.x == 0) {
        __threadfence();
        atomicAdd(&g_bar_cnt, 1u);
        while (*((volatile unsigned*)&g_bar_cnt) < target) __nanosleep(64);
        __threadfence();
    }
    __syncthreads();
}

// ---------------------------------------------------------------------------
// Mega kernel.
//  blocks [0, S_BLK):        zero+detect -> hist -> scan -> scatter, THEN
//                            join the gemm tile pool.
//  blocks [S_BLK, GRID_TOT): gemm tiles from a work-stealing counter.
//  gemm: g_Y = feat @ W, 128x128 tile, 8x8 reg tile held as 8x4 f32x2 pairs.
// ---------------------------------------------------------------------------
__global__ void __launch_bounds__(256, 2)
mega_kernel(const float* __restrict__ feat, const float* __restrict__ W,
            const void* __restrict__ srcp, const void* __restrict__ dstp) {
    __shared__ float sA[128 * 33];   // gemm A tile, stride-33 padded
    __shared__ float sB[32 * 128];   // gemm B tile [k][col]
    __shared__ int   ss[256];        // sort scan workspace

    const int tid = threadIdx.x;

    if (blockIdx.x < S_BLK) {
        // ================= SORT CHAIN =================
        const int b = blockIdx.x;
        const int st = b * 256 + tid;          // 0..16383
        const int NT = S_BLK * 256;            // 16384

        // ---- P0: zero histogram + detect index dtype ----
        for (int i = st; i < N_NODES; i += NT) g_count[i] = 0;
        if (b == 0 && tid < 32) {
            // int32 read as int64 packs two indices; high half is a random
            // node index (nonzero w.p. ~1-2e-5) -> out-of-range identifies it.
            const long long* s64 = (const long long*)srcp;
            const long long* d64 = (const long long*)dstp;
            int bad = 0;
#pragma unroll
            for (int r = 0; r < 2; r++) {
                int i = tid + r * 32;
                long long a = s64[i], c = d64[i];
                bad |= (a < 0 || a >= N_NODES || c < 0 || c >= N_NODES);
            }
            unsigned m = __ballot_sync(0xFFFFFFFFu, bad);
            if (tid == 0) g_is64 = (m == 0u);
        }
        sort_barrier(1u * S_BLK);

        // ---- P1: histogram over dst ----
        const int is64 = g_is64;
        if (is64) {
            const long long* dd = (const long long*)dstp;
            for (int e = st; e < N_EDGES; e += NT)
                atomicAdd(&g_count[(int)dd[e]], 1);
        } else {
            const int* dd = (const int*)dstp;
            for (int e = st; e < N_EDGES; e += NT)
                atomicAdd(&g_count[dd[e]], 1);
        }
        sort_barrier(2u * S_BLK);

        // ---- P2a: per-thread sums + block scan ----
        const int g0 = st * CHUNK;
        int csum = 0;
        int cv[CHUNK];
#pragma unroll
        for (int i = 0; i < CHUNK; i++) {
            int g = g0 + i;
            cv[i] = (g < N_NODES) ? g_count[g] : 0;
            csum += cv[i];
        }
        ss[tid] = csum;
        __syncthreads();
#pragma unroll
        for (int off = 1; off < 256; off <<= 1) {
            int v = ss[tid];
            int u = (tid >= off) ? ss[tid - off] : 0;
            __syncthreads();
            ss[tid] = v + u;
            __syncthreads();
        }
        const int texcl = ss[tid] - csum;
        if (tid == 255) g_bsum[b] = ss[255];
        sort_barrier(3u * S_BLK);

        // ---- P2b: block 0 scans the block totals ----
        if (b == 0) {
            int v0 = (tid < S_BLK) ? g_bsum[tid] : 0;
            ss[tid] = v0;
            __syncthreads();
#pragma unroll
            for (int off = 1; off < S_BLK; off <<= 1) {
                int v = ss[tid];
                int u = (tid >= off) ? ss[tid - off] : 0;
                __syncthreads();
                ss[tid] = v + u;
                __syncthreads();
            }
            if (tid < S_BLK) g_bbase[tid] = ss[tid] - v0;
        }
        sort_barrier(4u * S_BLK);

        // ---- P2c: write global exclusive offsets ----
        {
            int run = g_bbase[b] + texcl;
#pragma unroll
            for (int i = 0; i < CHUNK; i++) {
                int g = g0 + i;
                if (g < N_NODES) g_offset[g] = run;
                run += cv[i];
            }
        }
        sort_barrier(5u * S_BLK);

        // ---- P3: scatter src into dst-grouped order ----
        if (is64) {
            const long long* dd = (const long long*)dstp;
            const long long* sv = (const long long*)srcp;
            for (int e = st; e < N_EDGES; e += NT)
                g_src_sorted[atomicAdd(&g_offset[(int)dd[e]], 1)] = (int)sv[e];
        } else {
            const int* dd = (const int*)dstp;
            const int* sv = (const int*)srcp;
            for (int e = st; e < N_EDGES; e += NT)
                g_src_sorted[atomicAdd(&g_offset[dd[e]], 1)] = sv[e];
        }
        __syncthreads();
        // fall through: join the gemm tile pool
    }

    // ========== GEMM: g_Y = feat @ W (work-stealing, f32x2 FMA) ==========
    const int tx = tid & 15;          // col group (8 cols = 4 f32x2 pairs)
    const int ty = tid >> 4;          // row group (8 rows)
    const int kq = tid & 7;           // A stage: f4 index in k-chunk
    const int ar0 = tid >> 3;         // A stage: row 0..31
    const int c4 = tid & 31;          // B stage: f4 col
    const int kr0 = tid >> 5;         // B stage: k row 0..7

    __shared__ unsigned s_tile;
    for (;;) {
        __syncthreads();
        if (tid == 0) s_tile = atomicAdd(&g_tile, 1u);
        __syncthreads();
        const unsigned tile = s_tile;
        if (tile >= NGB) break;
        const int row0 = (int)tile * 128;

        unsigned long long acc2[8][4];   // acc2[i][jp] = cols (2jp, 2jp+1)
#pragma unroll
        for (int i = 0; i < 8; i++)
#pragma unroll
            for (int j = 0; j < 4; j++) acc2[i][j] = 0ull;

        for (int k0 = 0; k0 < D; k0 += 32) {
#pragma unroll
            for (int p = 0; p < 4; p++) {
                int r = ar0 + p * 32;
                int row = row0 + r;
                float4 v = make_float4(0.f, 0.f, 0.f, 0.f);
                if (row < N_NODES)
                    v = *(const float4*)(feat + (size_t)row * D + k0 + kq * 4);
                float* dst = &sA[r * 33 + kq * 4];
                dst[0] = v.x; dst[1] = v.y; dst[2] = v.z; dst[3] = v.w;
            }
#pragma unroll
            for (int p = 0; p < 4; p++) {
                int kr = kr0 + p * 8;
                *(float4*)(sB + kr * 128 + c4 * 4) =
                    *(const float4*)(W + (size_t)(k0 + kr) * D + c4 * 4);
            }
            __syncthreads();

#pragma unroll 8
            for (int k = 0; k < 32; k++) {
                // b: 2x LDS.128 reinterpreted as 4 packed f32x2 (cols 8tx..8tx+7)
                ulonglong2 bl0 = *(const ulonglong2*)(sB + k * 128 + tx * 8);
                ulonglong2 bl1 = *(const ulonglong2*)(sB + k * 128 + tx * 8 + 4);
                unsigned long long b2[4] = {bl0.x, bl0.y, bl1.x, bl1.y};
                // a: 8 scalar broadcasts, splatted to both lanes
                unsigned long long a2[8];
#pragma unroll
                for (int i = 0; i < 8; i++) {
                    float av = sA[(ty * 8 + i) * 33 + k];
                    SPLAT2(a2[i], av);
                }
#pragma unroll
                for (int i = 0; i < 8; i++)
#pragma unroll
                    for (int j = 0; j < 4; j++) FMA2(acc2[i][j], a2[i], b2[j]);
            }
            __syncthreads();
        }

#pragma unroll
        for (int i = 0; i < 8; i++) {
            int row = row0 + ty * 8 + i;
            if (row < N_NODES) {
                float f[8];
#pragma unroll
                for (int j = 0; j < 4; j++) UNPACK2(f[2 * j], f[2 * j + 1], acc2[i][j]);
                float* orow = g_Y + (size_t)row * D + tx * 8;
                *(float4*)(orow)     = make_float4(f[0], f[1], f[2], f[3]);
                *(float4*)(orow + 4) = make_float4(f[4], f[5], f[6], f[7]);
            }
        }
    }

    // ---- counter reset for next graph replay (last of all 296 blocks) ----
    __syncthreads();
    if (tid == 0) {
        __threadfence();
        unsigned old = atomicAdd(&g_done, 1u);
        if (old == GRID_TOT - 1) {
            g_tile = 0; g_bar_cnt = 0; g_done = 0;
        }
    }
}

// ---------------------------------------------------------------------------
// Aggregation: out[n] = sum_{e in seg(n)} Y[src_sorted[e]] + b.
// One warp per node, lane = float4 slice. At the L2 read cap (Y resident).
// Post-scatter g_offset[n] = global segment END; beg = end - count.
// ---------------------------------------------------------------------------
__global__ void __launch_bounds__(256) agg_kernel(const float* __restrict__ bias,
                                                  float* __restrict__ out) {
    int node = (blockIdx.x * blockDim.x + threadIdx.x) >> 5;
    int lane = threadIdx.x & 31;
    if (node >= N_NODES) return;

    const int end = g_offset[node];
    const int beg = end - g_count[node];

    float4 acc = make_float4(0.f, 0.f, 0.f, 0.f);
#pragma unroll 4
    for (int e = beg; e < end; e++) {
        int s = g_src_sorted[e];  // uniform across warp
        float4 v = ((const float4*)(g_Y + (size_t)s * D))[lane];
        acc.x += v.x; acc.y += v.y; acc.z += v.z; acc.w += v.w;
    }

    float4 bv = ((const float4*)bias)[lane];
    ((float4*)(out + (size_t)node * D))[lane] =
        make_float4(acc.x + bv.x, acc.y + bv.y, acc.z + bv.z, acc.w + bv.w);
}

// ---------------------------------------------------------------------------
// Launch: 2 kernels, graph-capturable (no sync, no alloc).
// ---------------------------------------------------------------------------
extern "C" void kernel_launch(void* const* d_in, const int* in_sizes, int n_in,
                              void* d_out, int out_size) {
    const float* feat = (const float*)d_in[0];  // [50000, 128] f32
    const void*  src  = d_in[1];                // [640000] int32/int64
    const void*  dst  = d_in[2];                // [640000] int32/int64
    const float* W    = (const float*)d_in[3];  // [128, 128] f32
    const float* b    = (const float*)d_in[4];  // [1, 128] f32
    float* out = (float*)d_out;                 // [50000, 128] f32

    mega_kernel<<<GRID_TOT, 256>>>(feat, W, src, dst);
    agg_kernel<<<(N_NODES * 32 + 255) / 256, 256>>>(b, out);
}

// round 8
// speedup vs baseline: 1.0478x; 1.0478x over previous
#include <cuda_runtime.h>
#include <cuda_bf16.h>

#define N_NODES 50000
#define D 128
#define N_EDGES 640000
#define S_BLK 64                       // sort blocks (wave-1 resident: < 148)
#define GRID_TOT 296                   // sort + gemm blocks
#define NGB ((N_NODES + 127) / 128)    // 391 gemm tiles
#define CHUNK 4                        // scan items per sort thread
#define NT (S_BLK * 256)               // sort threads = 16384

// ---- device scratch (no allocs allowed; zero-initialized) ----
__device__ float g_Y[(size_t)N_NODES * D];   // feat @ W   (25.6 MB)
__device__ int   g_count[N_NODES];           // degree histogram
__device__ int   g_offset[N_NODES];          // global excl. prefix; scatter mutates to end
__device__ int   g_bsum[S_BLK];              // per-sort-block totals
__device__ int   g_bbase[S_BLK];             // excl. scan of block totals
__device__ int   g_src_sorted[N_EDGES];      // src index grouped by dst
__device__ int   g_is64;                     // 1 if edge indices are int64
__device__ unsigned g_bar_cnt;               // sort barrier arrivals
__device__ unsigned g_tile;                  // gemm tile work-stealing counter
__device__ unsigned g_done;                  // end-of-kernel reset ticket

// Global spin barrier among the S_BLK sort blocks. target = phase * S_BLK.
__device__ __forceinline__ void sort_barrier(unsigned target) {
    __syncthreads();
    if (threadIdx.x == 0) {
        __threadfence();
        atomicAdd(&g_bar_cnt, 1u);
        while (*((volatile unsigned*)&g_bar_cnt) < target) __nanosleep(64);
        __threadfence();
    }
    __syncthreads();
}

// ---------------------------------------------------------------------------
// Mega kernel.
//  blocks [0, S_BLK):        zero+detect -> hist -> scan -> scatter, THEN
//                            join the gemm tile pool.
//  blocks [S_BLK, GRID_TOT): gemm tiles from a work-stealing counter.
//  gemm: g_Y = feat @ W, 128x128 tile, 8x8 register tile, Kc=32 in smem.
//  NOTE: no min-blocks clamp — reg cap at 128 caused inner-loop spills.
// ---------------------------------------------------------------------------
__global__ void __launch_bounds__(256)
mega_kernel(const float* __restrict__ feat, const float* __restrict__ W,
            const void* __restrict__ srcp, const void* __restrict__ dstp) {
    __shared__ float sA[128 * 33];   // gemm A tile, stride-33 padded
    __shared__ float sB[32 * 128];   // gemm B tile [k][col]
    __shared__ int   ss[256];        // sort scan workspace

    const int tid = threadIdx.x;

    if (blockIdx.x < S_BLK) {
        // ================= SORT CHAIN =================
        const int b = blockIdx.x;
        const int st = b * 256 + tid;          // 0..NT-1

        // ---- P0: zero histogram + detect index dtype ----
        for (int i = st; i < N_NODES; i += NT) g_count[i] = 0;
        if (b == 0 && tid < 32) {
            // int32 read as int64 packs two indices; high half is a random
            // node index (nonzero w.p. ~1-2e-5) -> out-of-range identifies it.
            const long long* s64 = (const long long*)srcp;
            const long long* d64 = (const long long*)dstp;
            int bad = 0;
#pragma unroll
            for (int r = 0; r < 2; r++) {
                int i = tid + r * 32;
                long long a = s64[i], c = d64[i];
                bad |= (a < 0 || a >= N_NODES || c < 0 || c >= N_NODES);
            }
            unsigned m = __ballot_sync(0xFFFFFFFFu, bad);
            if (tid == 0) g_is64 = (m == 0u);
        }
        sort_barrier(1u * S_BLK);

        // ---- P1: histogram over dst (4x batched for MLP) ----
        const int is64 = g_is64;
        {
            int e = st;
            if (is64) {
                const long long* dd = (const long long*)dstp;
                for (; e + 3 * NT < N_EDGES; e += 4 * NT) {
                    int d0 = (int)dd[e];
                    int d1 = (int)dd[e + NT];
                    int d2 = (int)dd[e + 2 * NT];
                    int d3 = (int)dd[e + 3 * NT];
                    atomicAdd(&g_count[d0], 1);
                    atomicAdd(&g_count[d1], 1);
                    atomicAdd(&g_count[d2], 1);
                    atomicAdd(&g_count[d3], 1);
                }
                for (; e < N_EDGES; e += NT) atomicAdd(&g_count[(int)dd[e]], 1);
            } else {
                const int* dd = (const int*)dstp;
                for (; e + 3 * NT < N_EDGES; e += 4 * NT) {
                    int d0 = dd[e];
                    int d1 = dd[e + NT];
                    int d2 = dd[e + 2 * NT];
                    int d3 = dd[e + 3 * NT];
                    atomicAdd(&g_count[d0], 1);
                    atomicAdd(&g_count[d1], 1);
                    atomicAdd(&g_count[d2], 1);
                    atomicAdd(&g_count[d3], 1);
                }
                for (; e < N_EDGES; e += NT) atomicAdd(&g_count[dd[e]], 1);
            }
        }
        sort_barrier(2u * S_BLK);

        // ---- P2a: per-thread sums + block scan ----
        const int g0 = st * CHUNK;
        int csum = 0;
        int cv[CHUNK];
#pragma unroll
        for (int i = 0; i < CHUNK; i++) {
            int g = g0 + i;
            cv[i] = (g < N_NODES) ? g_count[g] : 0;
            csum += cv[i];
        }
        ss[tid] = csum;
        __syncthreads();
#pragma unroll
        for (int off = 1; off < 256; off <<= 1) {
            int v = ss[tid];
            int u = (tid >= off) ? ss[tid - off] : 0;
            __syncthreads();
            ss[tid] = v + u;
            __syncthreads();
        }
        const int texcl = ss[tid] - csum;
        if (tid == 255) g_bsum[b] = ss[255];
        sort_barrier(3u * S_BLK);

        // ---- P2b: block 0 scans the block totals ----
        if (b == 0) {
            int v0 = (tid < S_BLK) ? g_bsum[tid] : 0;
            ss[tid] = v0;
            __syncthreads();
#pragma unroll
            for (int off = 1; off < S_BLK; off <<= 1) {
                int v = ss[tid];
                int u = (tid >= off) ? ss[tid - off] : 0;
                __syncthreads();
                ss[tid] = v + u;
                __syncthreads();
            }
            if (tid < S_BLK) g_bbase[tid] = ss[tid] - v0;
        }
        sort_barrier(4u * S_BLK);

        // ---- P2c: write global exclusive offsets ----
        {
            int run = g_bbase[b] + texcl;
#pragma unroll
            for (int i = 0; i < CHUNK; i++) {
                int g = g0 + i;
                if (g < N_NODES) g_offset[g] = run;
                run += cv[i];
            }
        }
        sort_barrier(5u * S_BLK);

        // ---- P3: scatter src into dst-grouped order (4x batched) ----
        {
            int e = st;
            if (is64) {
                const long long* dd = (const long long*)dstp;
                const long long* sv = (const long long*)srcp;
                for (; e + 3 * NT < N_EDGES; e += 4 * NT) {
                    int d0 = (int)dd[e],          s0 = (int)sv[e];
                    int d1 = (int)dd[e + NT],     s1 = (int)sv[e + NT];
                    int d2 = (int)dd[e + 2 * NT], s2 = (int)sv[e + 2 * NT];
                    int d3 = (int)dd[e + 3 * NT], s3 = (int)sv[e + 3 * NT];
                    int p0 = atomicAdd(&g_offset[d0], 1);
                    int p1 = atomicAdd(&g_offset[d1], 1);
                    int p2 = atomicAdd(&g_offset[d2], 1);
                    int p3 = atomicAdd(&g_offset[d3], 1);
                    g_src_sorted[p0] = s0;
                    g_src_sorted[p1] = s1;
                    g_src_sorted[p2] = s2;
                    g_src_sorted[p3] = s3;
                }
                for (; e < N_EDGES; e += NT)
                    g_src_sorted[atomicAdd(&g_offset[(int)dd[e]], 1)] = (int)sv[e];
            } else {
                const int* dd = (const int*)dstp;
                const int* sv = (const int*)srcp;
                for (; e + 3 * NT < N_EDGES; e += 4 * NT) {
                    int d0 = dd[e],          s0 = sv[e];
                    int d1 = dd[e + NT],     s1 = sv[e + NT];
                    int d2 = dd[e + 2 * NT], s2 = sv[e + 2 * NT];
                    int d3 = dd[e + 3 * NT], s3 = sv[e + 3 * NT];
                    int p0 = atomicAdd(&g_offset[d0], 1);
                    int p1 = atomicAdd(&g_offset[d1], 1);
                    int p2 = atomicAdd(&g_offset[d2], 1);
                    int p3 = atomicAdd(&g_offset[d3], 1);
                    g_src_sorted[p0] = s0;
                    g_src_sorted[p1] = s1;
                    g_src_sorted[p2] = s2;
                    g_src_sorted[p3] = s3;
                }
                for (; e < N_EDGES; e += NT)
                    g_src_sorted[atomicAdd(&g_offset[dd[e]], 1)] = sv[e];
            }
        }
        __syncthreads();
        // fall through: join the gemm tile pool
    }

    // ========== GEMM: g_Y = feat @ W (work-stealing, scalar FFMA) ==========
    const int tx = tid & 15;          // col group (8 cols)
    const int ty = tid >> 4;          // row group (8 rows)
    const int kq = tid & 7;           // A stage: f4 index in k-chunk
    const int ar0 = tid >> 3;         // A stage: row 0..31
    const int c4 = tid & 31;          // B stage: f4 col
    const int kr0 = tid >> 5;         // B stage: k row 0..7

    __shared__ unsigned s_tile;
    for (;;) {
        __syncthreads();
        if (tid == 0) s_tile = atomicAdd(&g_tile, 1u);
        __syncthreads();
        const unsigned tile = s_tile;
        if (tile >= NGB) break;
        const int row0 = (int)tile * 128;

        float acc[8][8];
#pragma unroll
        for (int i = 0; i < 8; i++)
#pragma unroll
            for (int j = 0; j < 8; j++) acc[i][j] = 0.f;

        for (int k0 = 0; k0 < D; k0 += 32) {
#pragma unroll
            for (int p = 0; p < 4; p++) {
                int r = ar0 + p * 32;
                int row = row0 + r;
                float4 v = make_float4(0.f, 0.f, 0.f, 0.f);
                if (row < N_NODES)
                    v = *(const float4*)(feat + (size_t)row * D + k0 + kq * 4);
                float* dst = &sA[r * 33 + kq * 4];
                dst[0] = v.x; dst[1] = v.y; dst[2] = v.z; dst[3] = v.w;
            }
#pragma unroll
            for (int p = 0; p < 4; p++) {
                int kr = kr0 + p * 8;
                *(float4*)(sB + kr * 128 + c4 * 4) =
                    *(const float4*)(W + (size_t)(k0 + kr) * D + c4 * 4);
            }
            __syncthreads();

#pragma unroll 8
            for (int k = 0; k < 32; k++) {
                float a[8];
#pragma unroll
                for (int i = 0; i < 8; i++) a[i] = sA[(ty * 8 + i) * 33 + k];
                float4 b0 = *(const float4*)(sB + k * 128 + tx * 8);
                float4 b1 = *(const float4*)(sB + k * 128 + tx * 8 + 4);
                float bb[8] = {b0.x, b0.y, b0.z, b0.w, b1.x, b1.y, b1.z, b1.w};
#pragma unroll
                for (int i = 0; i < 8; i++)
#pragma unroll
                    for (int j = 0; j < 8; j++) acc[i][j] += a[i] * bb[j];
            }
            __syncthreads();
        }

#pragma unroll
        for (int i = 0; i < 8; i++) {
            int row = row0 + ty * 8 + i;
            if (row < N_NODES) {
                float* orow = g_Y + (size_t)row * D + tx * 8;
                *(float4*)(orow)     = make_float4(acc[i][0], acc[i][1], acc[i][2], acc[i][3]);
                *(float4*)(orow + 4) = make_float4(acc[i][4], acc[i][5], acc[i][6], acc[i][7]);
            }
        }
    }

    // ---- counter reset for next graph replay (last of all blocks) ----
    __syncthreads();
    if (tid == 0) {
        __threadfence();
        unsigned old = atomicAdd(&g_done, 1u);
        if (old == GRID_TOT - 1) {
            g_tile = 0; g_bar_cnt = 0; g_done = 0;
        }
    }
}

// ---------------------------------------------------------------------------
// Aggregation: out[n] = sum_{e in seg(n)} Y[src_sorted[e]] + b.
// One warp per node, lane = float4 slice. At the practical L2 read cap
// (327 MB @ ~12 TB/s). Post-scatter g_offset[n] = segment END.
// ---------------------------------------------------------------------------
__global__ void __launch_bounds__(256) agg_kernel(const float* __restrict__ bias,
                                                  float* __restrict__ out) {
    int node = (blockIdx.x * blockDim.x + threadIdx.x) >> 5;
    int lane = threadIdx.x & 31;
    if (node >= N_NODES) return;

    const int end = g_offset[node];
    const int beg = end - g_count[node];

    float4 acc = make_float4(0.f, 0.f, 0.f, 0.f);
#pragma unroll 4
    for (int e = beg; e < end; e++) {
        int s = g_src_sorted[e];  // uniform across warp
        float4 v = ((const float4*)(g_Y + (size_t)s * D))[lane];
        acc.x += v.x; acc.y += v.y; acc.z += v.z; acc.w += v.w;
    }

    float4 bv = ((const float4*)bias)[lane];
    ((float4*)(out + (size_t)node * D))[lane] =
        make_float4(acc.x + bv.x, acc.y + bv.y, acc.z + bv.z, acc.w + bv.w);
}

// ---------------------------------------------------------------------------
// Launch: 2 kernels, graph-capturable (no sync, no alloc).
// ---------------------------------------------------------------------------
extern "C" void kernel_launch(void* const* d_in, const int* in_sizes, int n_in,
                              void* d_out, int out_size) {
    const float* feat = (const float*)d_in[0];  // [50000, 128] f32
    const void*  src  = d_in[1];                // [640000] int32/int64
    const void*  dst  = d_in[2];                // [640000] int32/int64
    const float* W    = (const float*)d_in[3];  // [128, 128] f32
    const float* b    = (const float*)d_in[4];  // [1, 128] f32
    float* out = (float*)d_out;                 // [50000, 128] f32

    mega_kernel<<<GRID_TOT, 256>>>(feat, W, src, dst);
    agg_kernel<<<(N_NODES * 32 + 255) / 256, 256>>>(b, out);
}